// round 15
// baseline (speedup 1.0000x reference)
#include <cuda_runtime.h>

// Problem constants
#define N1    192
#define N2    48
#define D_IN  1024
#define D1    1025          // D_IN + 1 (bias row)
#define D_OUT 512
#define LAM   0.001f
#define LR    0.01f
#define ITRS  100

#define NCH   16            // d-dimension chunks for the reduction pass
#define DPC   65            // rows per chunk (15 full chunks of 65, last = 50)
#define K4    (N1/4)        // 48 float4 columns

#define NB_RED  (N2*NCH)    // 768 reduce blocks
#define NB_PRED 64          // 64 pred blocks (8 warps x 64 = 512 rows)

// Deterministic scratch (no device-side allocation allowed)
__device__ float4 g_pA4[NCH * N2 * K4];   // partial raw A (pre-normalization)
__device__ float4 g_pQ4[NCH * N2 * K4];   // partial q = h1^T W0
__device__ float  g_pS [NCH * N2];        // partial s0 = ||W0||_F^2
__device__ float  g_beta[N2];
__device__ float4 g_u4 [N2 * K4];
__device__ unsigned int g_cnt[N2];        // zero at load; electing block resets

// ---------------------------------------------------------------------------
// Pass A (fused): partial reductions over We/W0 + pred + PER-GROUP last-block
// finalize (collapsed GD). The 16th block of group n to finish runs the
// finalize for group n only -> 48 finalizes run concurrently on 48 SMs,
// hidden under the other groups' streaming tail.
// ---------------------------------------------------------------------------
__global__ void __launch_bounds__(256) fusedA_kernel(
    const float* __restrict__ x,
    const float* __restrict__ We,
    const float* __restrict__ W0,
    const float* __restrict__ Wp,
    const float* __restrict__ bp,
    float* __restrict__ out)
{
    if (blockIdx.x < NB_RED) {
        const int n = blockIdx.x % N2;
        const int c = blockIdx.x / N2;
        const int t = threadIdx.x;

        __shared__ float4 smA[5][K4];
        __shared__ float4 smQ[5][K4];
        __shared__ float  smS[8];
        __shared__ int    sLast;

        float s = 0.f;
        if (t < 240) {
            const int k4 = t % K4;
            const int dr = t / K4;                 // 0..4
            const int d0 = c * DPC + dr;
            const int iters = (c < NCH - 1) ? 13 : 10;   // 65 or 50 rows / 5

            float4 a4 = make_float4(0.f, 0.f, 0.f, 0.f);
            float4 q4 = make_float4(0.f, 0.f, 0.f, 0.f);

            const float4* we4 = (const float4*)We + (size_t)n * D1 * K4 + k4;
            const float4* w04 = (const float4*)W0 + (size_t)n * D1 * K4 + k4;

            #pragma unroll 4
            for (int j = 0; j < iters; ++j) {
                const int d = d0 + 5 * j;
                float  h  = (d < D_IN) ? __ldg(x + d) : 1.0f;
                float4 wv = __ldg(we4 + (size_t)d * K4);
                float4 w0 = __ldg(w04 + (size_t)d * K4);
                a4.x = fmaf(h, wv.x, a4.x); a4.y = fmaf(h, wv.y, a4.y);
                a4.z = fmaf(h, wv.z, a4.z); a4.w = fmaf(h, wv.w, a4.w);
                q4.x = fmaf(h, w0.x, q4.x); q4.y = fmaf(h, w0.y, q4.y);
                q4.z = fmaf(h, w0.z, q4.z); q4.w = fmaf(h, w0.w, q4.w);
                s = fmaf(w0.x, w0.x, s); s = fmaf(w0.y, w0.y, s);
                s = fmaf(w0.z, w0.z, s); s = fmaf(w0.w, w0.w, s);
            }
            smA[dr][k4] = a4;
            smQ[dr][k4] = q4;
        }

        // block-reduce s (8 warps; idle threads carry 0)
        #pragma unroll
        for (int o = 16; o > 0; o >>= 1) s += __shfl_down_sync(0xffffffffu, s, o);
        if ((t & 31) == 0) smS[t >> 5] = s;
        __syncthreads();

        if (t < K4) {
            float4 a4 = smA[0][t], q4 = smQ[0][t];
            #pragma unroll
            for (int r = 1; r < 5; ++r) {
                float4 a = smA[r][t], q = smQ[r][t];
                a4.x += a.x; a4.y += a.y; a4.z += a.z; a4.w += a.w;
                q4.x += q.x; q4.y += q.y; q4.z += q.z; q4.w += q.w;
            }
            g_pA4[(c * N2 + n) * K4 + t] = a4;
            g_pQ4[(c * N2 + n) * K4 + t] = q4;
        }
        if (t == 0) {
            float tot = 0.f;
            #pragma unroll
            for (int i = 0; i < 8; ++i) tot += smS[i];
            g_pS[c * N2 + n] = tot;
        }

        // ---- per-group last-block election ----
        __threadfence();
        __syncthreads();
        if (t == 0) {
            unsigned prev = atomicAdd(&g_cnt[n], 1u);
            sLast = (prev == NCH - 1) ? 1 : 0;
        }
        __syncthreads();
        if (!sLast) return;
        if (t == 0) g_cnt[n] = 0;      // reset for next graph replay
        __threadfence();               // acquire: partials of all 16 blocks visible

        // ===== finalize for group n (256 threads; data L2-hot, ~48 KB) =====
        const float* pA = (const float*)g_pA4;
        const float* pQ = (const float*)g_pQ4;

        float A = 0.f, q = 0.f;
        if (t < N1) {
            #pragma unroll
            for (int ch = 0; ch < NCH; ++ch) {
                A += __ldg(pA + (ch * N2 + n) * N1 + t);
                q += __ldg(pQ + (ch * N2 + n) * N1 + t);
            }
        }
        float s0p = (t < NCH) ? __ldg(g_pS + t * N2 + n) : 0.f;

        float xp = 0.f;
        for (int i = t; i < D_IN; i += 256) { float v = __ldg(x + i); xp = fmaf(v, v, xp); }

        float aa = A * A, qq = q * q, qa = q * A;
        __shared__ float sm5[8][5];
        __shared__ float bc[2];
        #pragma unroll
        for (int o = 16; o > 0; o >>= 1) {
            aa  += __shfl_down_sync(0xffffffffu, aa,  o);
            qq  += __shfl_down_sync(0xffffffffu, qq,  o);
            qa  += __shfl_down_sync(0xffffffffu, qa,  o);
            xp  += __shfl_down_sync(0xffffffffu, xp,  o);
            s0p += __shfl_down_sync(0xffffffffu, s0p, o);
        }
        if ((t & 31) == 0) {
            int w = t >> 5;
            sm5[w][0] = aa; sm5[w][1] = qq; sm5[w][2] = qa; sm5[w][3] = xp; sm5[w][4] = s0p;
        }
        __syncthreads();

        if (t == 0) {
            float taa = 0.f, tqq = 0.f, tqa = 0.f, txp = 0.f, ts0 = 0.f;
            #pragma unroll
            for (int i = 0; i < 8; ++i) {
                taa += sm5[i][0]; tqq += sm5[i][1]; tqa += sm5[i][2];
                txp += sm5[i][3]; ts0 += sm5[i][4];
            }
            const float hh    = txp + 1.0f;            // ||h1||^2
            const float invNa = rsqrtf(taa);           // 1/||A_raw||
            const float qA    = tqa * invNa;           // q . Ahat
            const float cc    = 2.0f * LR;
            const float eps   = LR * LAM;

            float p = 0.f, aH = 0.f, beta = 1.0f;
            for (int it = 0; it < ITRS; ++it) {
                float qu = p * tqq + aH * qA;                          // q.u
                float uu = p * p * tqq + 2.0f * p * aH * qA + aH * aH; // ||u||^2
                float v  = beta * beta * ts0 + 2.0f * beta * qu + hh * uu;
                float alpha = 1.0f - eps * rsqrtf(v);                  // 1 - eps/||W||
                float m = alpha - cc * hh;
                float pn = m * p - cc * beta;
                aH = m * aH + cc;
                p = pn;
                beta *= alpha;
            }
            bc[0] = p;
            bc[1] = aH * invNa;    // coefficient on A_raw
            g_beta[n] = beta;
        }
        __syncthreads();

        if (t < N1) ((float*)g_u4)[n * N1 + t] = bc[0] * q + bc[1] * A;
    } else {
        // --- pred role: one warp per output row, float4, unrolled ---
        const int warp = (blockIdx.x - NB_RED) * 8 + (threadIdx.x >> 5);
        const int lane = threadIdx.x & 31;
        const float4* row = (const float4*)(Wp + (size_t)warp * D_IN);
        const float4* x4  = (const float4*)x;
        float sacc = 0.f;
        #pragma unroll
        for (int i = 0; i < 8; ++i) {
            float4 w = __ldg(row + lane + i * 32);
            float4 v = __ldg(x4  + lane + i * 32);
            sacc = fmaf(w.x, v.x, sacc); sacc = fmaf(w.y, v.y, sacc);
            sacc = fmaf(w.z, v.z, sacc); sacc = fmaf(w.w, v.w, sacc);
        }
        #pragma unroll
        for (int o = 16; o > 0; o >>= 1) sacc += __shfl_down_sync(0xffffffffu, sacc, o);
        if (lane == 0) out[warp] = sacc + __ldg(bp + warp);
    }
}

// ---------------------------------------------------------------------------
// Pass C: W_all = beta_n * W0 + h1 * u^T.
// (n, chunk) x (k4, dr) layout: uv and beta hoisted to registers,
// no div/mod in the stream loop. Pure LDG.128 -> FFMA -> STG.128.
// ---------------------------------------------------------------------------
__global__ void __launch_bounds__(256) outC_kernel(
    const float* __restrict__ x,
    const float* __restrict__ W0,
    float* __restrict__ out)   // points at d_out + 512
{
    const int n = blockIdx.x % N2;
    const int c = blockIdx.x / N2;
    const int t = threadIdx.x;

    if (t < 240) {
        const int k4 = t % K4;
        const int dr = t / K4;                 // 0..4
        const int d0 = c * DPC + dr;
        const int iters = (c < NCH - 1) ? 13 : 10;   // 65 or 50 rows / 5

        const float4 uv = g_u4[n * K4 + k4];   // hoisted: constant per thread
        const float  b  = g_beta[n];

        const size_t base = (size_t)n * D1 * K4 + k4;
        const float4* w04 = (const float4*)W0 + base;
        float4*       o4  = (float4*)out + base;

        #pragma unroll 4
        for (int j = 0; j < iters; ++j) {
            const int d = d0 + 5 * j;
            const float h = (d < D_IN) ? __ldg(x + d) : 1.0f;
            float4 w = __ldg(w04 + (size_t)d * K4);
            float4 o;
            o.x = fmaf(b, w.x, h * uv.x);
            o.y = fmaf(b, w.y, h * uv.y);
            o.z = fmaf(b, w.z, h * uv.z);
            o.w = fmaf(b, w.w, h * uv.w);
            o4[(size_t)d * K4] = o;
        }
    }
}

// ---------------------------------------------------------------------------
extern "C" void kernel_launch(void* const* d_in, const int* in_sizes, int n_in,
                              void* d_out, int out_size)
{
    const float* x  = (const float*)d_in[0];
    const float* We = (const float*)d_in[1];
    const float* W0 = (const float*)d_in[2];
    const float* Wp = (const float*)d_in[3];
    const float* bp = (const float*)d_in[4];
    float* out = (float*)d_out;

    // Pass A: stream We + W0 -> partials + pred + per-group finalize
    fusedA_kernel<<<NB_RED + NB_PRED, 256>>>(x, We, W0, Wp, bp, out);

    // Pass C: write W_all (after the 512 pred floats)
    outC_kernel<<<NB_RED, 256>>>(x, W0, out + D_OUT);
}

// round 16
// speedup vs baseline: 1.1134x; 1.1134x over previous
#include <cuda_runtime.h>

// Problem constants
#define N1    192
#define N2    48
#define D_IN  1024
#define D1    1025          // D_IN + 1 (bias row)
#define D_OUT 512
#define LAM   0.001f
#define LR    0.01f
#define ITRS  100

#define NCH   16            // d-dimension chunks for pass A
#define DPC   65            // rows per chunk (15 full chunks of 65, last = 50)
#define K4    (N1/4)        // 48 float4 columns

#define NCHC  32            // finer chunks for pass C (2-wave balance)
#define DPCC  33            // rows per C-chunk (31 full chunks of 33, last = 2)

#define NB_RED  (N2*NCH)    // 768 reduce blocks
#define NB_PRED 64          // 64 pred blocks (8 warps x 64 = 512 rows)
#define NB_C    (N2*NCHC)   // 1536 output blocks

// Deterministic scratch (no device-side allocation allowed)
__device__ float4 g_pA4[NCH * N2 * K4];   // partial raw A (pre-normalization)
__device__ float4 g_pQ4[NCH * N2 * K4];   // partial q = h1^T W0
__device__ float  g_pS [NCH * N2];        // partial s0 = ||W0||_F^2
__device__ float  g_beta[N2];
__device__ float4 g_u4 [N2 * K4];

// ---------------------------------------------------------------------------
// Pass A (fused): partial reductions over We/W0  +  pred = x@Wp^T + bp.
// Reduce blocks: (group n, chunk c), 240 active threads as (k4:48, dr:5),
// float4 loads, unroll 4 -> 8 independent LDG.128 in flight per thread.
// ---------------------------------------------------------------------------
__global__ void __launch_bounds__(256) fusedA_kernel(
    const float* __restrict__ x,
    const float* __restrict__ We,
    const float* __restrict__ W0,
    const float* __restrict__ Wp,
    const float* __restrict__ bp,
    float* __restrict__ out)
{
    if (blockIdx.x < NB_RED) {
        const int n = blockIdx.x % N2;
        const int c = blockIdx.x / N2;
        const int t = threadIdx.x;

        __shared__ float4 smA[5][K4];
        __shared__ float4 smQ[5][K4];
        __shared__ float  smS[8];

        float s = 0.f;
        if (t < 240) {
            const int k4 = t % K4;
            const int dr = t / K4;                 // 0..4
            const int d0 = c * DPC + dr;
            const int iters = (c < NCH - 1) ? 13 : 10;   // 65 or 50 rows / 5

            float4 a4 = make_float4(0.f, 0.f, 0.f, 0.f);
            float4 q4 = make_float4(0.f, 0.f, 0.f, 0.f);

            const float4* we4 = (const float4*)We + (size_t)n * D1 * K4 + k4;
            const float4* w04 = (const float4*)W0 + (size_t)n * D1 * K4 + k4;

            #pragma unroll 4
            for (int j = 0; j < iters; ++j) {
                const int d = d0 + 5 * j;
                float  h  = (d < D_IN) ? __ldg(x + d) : 1.0f;
                float4 wv = __ldg(we4 + (size_t)d * K4);
                float4 w0 = __ldg(w04 + (size_t)d * K4);
                a4.x = fmaf(h, wv.x, a4.x); a4.y = fmaf(h, wv.y, a4.y);
                a4.z = fmaf(h, wv.z, a4.z); a4.w = fmaf(h, wv.w, a4.w);
                q4.x = fmaf(h, w0.x, q4.x); q4.y = fmaf(h, w0.y, q4.y);
                q4.z = fmaf(h, w0.z, q4.z); q4.w = fmaf(h, w0.w, q4.w);
                s = fmaf(w0.x, w0.x, s); s = fmaf(w0.y, w0.y, s);
                s = fmaf(w0.z, w0.z, s); s = fmaf(w0.w, w0.w, s);
            }
            smA[dr][k4] = a4;
            smQ[dr][k4] = q4;
        }

        // block-reduce s (8 warps; idle threads carry 0)
        #pragma unroll
        for (int o = 16; o > 0; o >>= 1) s += __shfl_down_sync(0xffffffffu, s, o);
        if ((t & 31) == 0) smS[t >> 5] = s;
        __syncthreads();

        if (t < K4) {
            float4 a4 = smA[0][t], q4 = smQ[0][t];
            #pragma unroll
            for (int r = 1; r < 5; ++r) {
                float4 a = smA[r][t], q = smQ[r][t];
                a4.x += a.x; a4.y += a.y; a4.z += a.z; a4.w += a.w;
                q4.x += q.x; q4.y += q.y; q4.z += q.z; q4.w += q.w;
            }
            g_pA4[(c * N2 + n) * K4 + t] = a4;
            g_pQ4[(c * N2 + n) * K4 + t] = q4;
        }
        if (t == 0) {
            float tot = 0.f;
            #pragma unroll
            for (int i = 0; i < 8; ++i) tot += smS[i];
            g_pS[c * N2 + n] = tot;
        }
    } else {
        // --- pred role: one warp per output row, float4, unrolled ---
        const int warp = (blockIdx.x - NB_RED) * 8 + (threadIdx.x >> 5);
        const int lane = threadIdx.x & 31;
        const float4* row = (const float4*)(Wp + (size_t)warp * D_IN);
        const float4* x4  = (const float4*)x;
        float sacc = 0.f;
        #pragma unroll
        for (int i = 0; i < 8; ++i) {
            float4 w = __ldg(row + lane + i * 32);
            float4 v = __ldg(x4  + lane + i * 32);
            sacc = fmaf(w.x, v.x, sacc); sacc = fmaf(w.y, v.y, sacc);
            sacc = fmaf(w.z, v.z, sacc); sacc = fmaf(w.w, v.w, sacc);
        }
        #pragma unroll
        for (int o = 16; o > 0; o >>= 1) sacc += __shfl_down_sync(0xffffffffu, sacc, o);
        if (lane == 0) out[warp] = sacc + __ldg(bp + warp);
    }
}

// ---------------------------------------------------------------------------
// Pass B: finalize scalars + fully-collapsed GD (48 blocks x 192 threads).
// u_t = p_t * q + a_t * Ahat (exact span collapse) -> scalar recurrence.
// ---------------------------------------------------------------------------
__global__ void __launch_bounds__(N1) iterB_kernel(const float* __restrict__ x)
{
    const int n = blockIdx.x;
    const int k = threadIdx.x;

    const float* pA = (const float*)g_pA4;
    const float* pQ = (const float*)g_pQ4;

    float A = 0.f, q = 0.f;
    #pragma unroll
    for (int c = 0; c < NCH; ++c) {
        A += __ldg(pA + (c * N2 + n) * N1 + k);
        q += __ldg(pQ + (c * N2 + n) * N1 + k);
    }
    float s0p = (k < NCH) ? __ldg(g_pS + k * N2 + n) : 0.f;

    float xp = 0.f;
    for (int i = k; i < D_IN; i += N1) { float v = __ldg(x + i); xp = fmaf(v, v, xp); }

    // fused 5-value reduction: aa, qq, qa, xp, s0
    float aa = A * A, qq = q * q, qa = q * A;
    __shared__ float sm[6][5];
    __shared__ float bc[2];
    #pragma unroll
    for (int o = 16; o > 0; o >>= 1) {
        aa  += __shfl_down_sync(0xffffffffu, aa,  o);
        qq  += __shfl_down_sync(0xffffffffu, qq,  o);
        qa  += __shfl_down_sync(0xffffffffu, qa,  o);
        xp  += __shfl_down_sync(0xffffffffu, xp,  o);
        s0p += __shfl_down_sync(0xffffffffu, s0p, o);
    }
    if ((k & 31) == 0) {
        int w = k >> 5;
        sm[w][0] = aa; sm[w][1] = qq; sm[w][2] = qa; sm[w][3] = xp; sm[w][4] = s0p;
    }
    __syncthreads();

    if (k == 0) {
        float taa = 0.f, tqq = 0.f, tqa = 0.f, txp = 0.f, ts0 = 0.f;
        #pragma unroll
        for (int i = 0; i < 6; ++i) {
            taa += sm[i][0]; tqq += sm[i][1]; tqa += sm[i][2];
            txp += sm[i][3]; ts0 += sm[i][4];
        }
        const float hh    = txp + 1.0f;            // ||h1||^2
        const float invNa = rsqrtf(taa);           // 1/||A_raw||
        const float qA    = tqa * invNa;           // q . Ahat
        const float cc    = 2.0f * LR;
        const float eps   = LR * LAM;

        float p = 0.f, aH = 0.f, beta = 1.0f;
        for (int t = 0; t < ITRS; ++t) {
            float qu = p * tqq + aH * qA;                          // q.u
            float uu = p * p * tqq + 2.0f * p * aH * qA + aH * aH; // ||u||^2
            float v  = beta * beta * ts0 + 2.0f * beta * qu + hh * uu;
            float alpha = 1.0f - eps * rsqrtf(v);                  // 1 - eps/||W||
            float m = alpha - cc * hh;
            float pn = m * p - cc * beta;
            aH = m * aH + cc;
            p = pn;
            beta *= alpha;
        }
        bc[0] = p;
        bc[1] = aH * invNa;    // coefficient on A_raw
        g_beta[n] = beta;
    }
    __syncthreads();

    ((float*)g_u4)[n * N1 + k] = bc[0] * q + bc[1] * A;
}

// ---------------------------------------------------------------------------
// Pass C: W_all = beta_n * W0 + h1 * u^T.
// Finer blocks than A (NCHC=32 -> 1536 blocks, 2 waves) for work-stealing
// balance; prologue is only 2 loads so the finer split is nearly free.
// Streaming stores (__stcs) keep L2 capacity for the W0 reads.
// ---------------------------------------------------------------------------
__global__ void __launch_bounds__(256) outC_kernel(
    const float* __restrict__ x,
    const float* __restrict__ W0,
    float* __restrict__ out)   // points at d_out + 512
{
    const int n = blockIdx.x % N2;
    const int c = blockIdx.x / N2;
    const int t = threadIdx.x;

    if (t < 240) {
        const int k4 = t % K4;
        const int dr = t / K4;                 // 0..4
        const int d0 = c * DPCC;
        const int dEnd = (d0 + DPCC < D1) ? (d0 + DPCC) : D1;

        const float4 uv = g_u4[n * K4 + k4];   // hoisted: constant per thread
        const float  b  = g_beta[n];

        const size_t base = (size_t)n * D1 * K4 + k4;
        const float4* w04 = (const float4*)W0 + base;
        float4*       o4  = (float4*)out + base;

        #pragma unroll 4
        for (int d = d0 + dr; d < dEnd; d += 5) {
            const float h = (d < D_IN) ? __ldg(x + d) : 1.0f;
            float4 w = __ldg(w04 + (size_t)d * K4);
            float4 o;
            o.x = fmaf(b, w.x, h * uv.x);
            o.y = fmaf(b, w.y, h * uv.y);
            o.z = fmaf(b, w.z, h * uv.z);
            o.w = fmaf(b, w.w, h * uv.w);
            __stcs(o4 + (size_t)d * K4, o);    // streaming store: evict-first
        }
    }
}

// ---------------------------------------------------------------------------
extern "C" void kernel_launch(void* const* d_in, const int* in_sizes, int n_in,
                              void* d_out, int out_size)
{
    const float* x  = (const float*)d_in[0];
    const float* We = (const float*)d_in[1];
    const float* W0 = (const float*)d_in[2];
    const float* Wp = (const float*)d_in[3];
    const float* bp = (const float*)d_in[4];
    float* out = (float*)d_out;

    // Pass A: stream We + W0 -> partials; pred fused in as extra blocks
    fusedA_kernel<<<NB_RED + NB_PRED, 256>>>(x, We, W0, Wp, bp, out);

    // Pass B: scalar-collapsed GD -> beta, u (48 blocks, parallel)
    iterB_kernel<<<N2, N1>>>(x);

    // Pass C: write W_all (after the 512 pred floats), 2-wave balanced
    outC_kernel<<<NB_C, 256>>>(x, W0, out + D_OUT);
}

// round 17
// speedup vs baseline: 1.1363x; 1.0206x over previous
#include <cuda_runtime.h>

// Problem constants
#define N1    192
#define N2    48
#define D_IN  1024
#define D1    1025          // D_IN + 1 (bias row)
#define D_OUT 512
#define LAM   0.001f
#define LR    0.01f
#define ITRS  100

#define NCH   16            // d-dimension chunks for pass A
#define DPC   65            // rows per chunk (15 full chunks of 65, last = 50)
#define K4    (N1/4)        // 48 float4 columns

#define NCHC  32            // finer chunks for pass C (2-wave balance)
#define DPCC  33            // rows per C-chunk (31 full chunks of 33, last = 2)

#define NB_RED  (N2*NCH)    // 768 reduce blocks
#define NB_PRED 64          // 64 pred blocks (8 warps x 64 = 512 rows)
#define NB_C    (N2*NCHC)   // 1536 output blocks

// Deterministic scratch (no device-side allocation allowed)
__device__ float4 g_pA4[NCH * N2 * K4];   // partial raw A (pre-normalization)
__device__ float4 g_pQ4[NCH * N2 * K4];   // partial q = h1^T W0
__device__ float  g_pS [NCH * N2];        // partial s0 = ||W0||_F^2
__device__ float  g_beta[N2];
__device__ float4 g_u4 [N2 * K4];

// ---------------------------------------------------------------------------
// Pass A (fused): partial reductions over We/W0  +  pred = x@Wp^T + bp.
// ---------------------------------------------------------------------------
__global__ void __launch_bounds__(256) fusedA_kernel(
    const float* __restrict__ x,
    const float* __restrict__ We,
    const float* __restrict__ W0,
    const float* __restrict__ Wp,
    const float* __restrict__ bp,
    float* __restrict__ out)
{
    if (blockIdx.x < NB_RED) {
        const int n = blockIdx.x % N2;
        const int c = blockIdx.x / N2;
        const int t = threadIdx.x;

        __shared__ float4 smA[5][K4];
        __shared__ float4 smQ[5][K4];
        __shared__ float  smS[8];

        float s = 0.f;
        if (t < 240) {
            const int k4 = t % K4;
            const int dr = t / K4;                 // 0..4
            const int d0 = c * DPC + dr;
            const int iters = (c < NCH - 1) ? 13 : 10;   // 65 or 50 rows / 5

            float4 a4 = make_float4(0.f, 0.f, 0.f, 0.f);
            float4 q4 = make_float4(0.f, 0.f, 0.f, 0.f);

            const float4* we4 = (const float4*)We + (size_t)n * D1 * K4 + k4;
            const float4* w04 = (const float4*)W0 + (size_t)n * D1 * K4 + k4;

            #pragma unroll 4
            for (int j = 0; j < iters; ++j) {
                const int d = d0 + 5 * j;
                float  h  = (d < D_IN) ? __ldg(x + d) : 1.0f;
                float4 wv = __ldg(we4 + (size_t)d * K4);
                float4 w0 = __ldg(w04 + (size_t)d * K4);
                a4.x = fmaf(h, wv.x, a4.x); a4.y = fmaf(h, wv.y, a4.y);
                a4.z = fmaf(h, wv.z, a4.z); a4.w = fmaf(h, wv.w, a4.w);
                q4.x = fmaf(h, w0.x, q4.x); q4.y = fmaf(h, w0.y, q4.y);
                q4.z = fmaf(h, w0.z, q4.z); q4.w = fmaf(h, w0.w, q4.w);
                s = fmaf(w0.x, w0.x, s); s = fmaf(w0.y, w0.y, s);
                s = fmaf(w0.z, w0.z, s); s = fmaf(w0.w, w0.w, s);
            }
            smA[dr][k4] = a4;
            smQ[dr][k4] = q4;
        }

        // block-reduce s (8 warps; idle threads carry 0)
        #pragma unroll
        for (int o = 16; o > 0; o >>= 1) s += __shfl_down_sync(0xffffffffu, s, o);
        if ((t & 31) == 0) smS[t >> 5] = s;
        __syncthreads();

        if (t < K4) {
            float4 a4 = smA[0][t], q4 = smQ[0][t];
            #pragma unroll
            for (int r = 1; r < 5; ++r) {
                float4 a = smA[r][t], q = smQ[r][t];
                a4.x += a.x; a4.y += a.y; a4.z += a.z; a4.w += a.w;
                q4.x += q.x; q4.y += q.y; q4.z += q.z; q4.w += q.w;
            }
            g_pA4[(c * N2 + n) * K4 + t] = a4;
            g_pQ4[(c * N2 + n) * K4 + t] = q4;
        }
        if (t == 0) {
            float tot = 0.f;
            #pragma unroll
            for (int i = 0; i < 8; ++i) tot += smS[i];
            g_pS[c * N2 + n] = tot;
        }
    } else {
        // --- pred role: one warp per output row, float4, unrolled ---
        const int warp = (blockIdx.x - NB_RED) * 8 + (threadIdx.x >> 5);
        const int lane = threadIdx.x & 31;
        const float4* row = (const float4*)(Wp + (size_t)warp * D_IN);
        const float4* x4  = (const float4*)x;
        float sacc = 0.f;
        #pragma unroll
        for (int i = 0; i < 8; ++i) {
            float4 w = __ldg(row + lane + i * 32);
            float4 v = __ldg(x4  + lane + i * 32);
            sacc = fmaf(w.x, v.x, sacc); sacc = fmaf(w.y, v.y, sacc);
            sacc = fmaf(w.z, v.z, sacc); sacc = fmaf(w.w, v.w, sacc);
        }
        #pragma unroll
        for (int o = 16; o > 0; o >>= 1) sacc += __shfl_down_sync(0xffffffffu, sacc, o);
        if (lane == 0) out[warp] = sacc + __ldg(bp + warp);
    }
}

// ---------------------------------------------------------------------------
// Pass B: finalize scalars + fully-collapsed GD (48 blocks x 192 threads).
// PDL: x-prologue runs before cudaGridDependencySynchronize() so it overlaps
// pass A's drain; A's outputs are only read after the sync.
// ---------------------------------------------------------------------------
__global__ void __launch_bounds__(N1) iterB_kernel(const float* __restrict__ x)
{
    const int n = blockIdx.x;
    const int k = threadIdx.x;

    // -------- upstream-independent prologue (overlaps A via PDL) --------
    float xp = 0.f;
    for (int i = k; i < D_IN; i += N1) { float v = __ldg(x + i); xp = fmaf(v, v, xp); }

    cudaGridDependencySynchronize();   // wait for pass A's partials

    const float* pA = (const float*)g_pA4;
    const float* pQ = (const float*)g_pQ4;

    float A = 0.f, q = 0.f;
    #pragma unroll
    for (int c = 0; c < NCH; ++c) {
        A += __ldg(pA + (c * N2 + n) * N1 + k);
        q += __ldg(pQ + (c * N2 + n) * N1 + k);
    }
    float s0p = (k < NCH) ? __ldg(g_pS + k * N2 + n) : 0.f;

    // fused 5-value reduction: aa, qq, qa, xp, s0
    float aa = A * A, qq = q * q, qa = q * A;
    __shared__ float sm[6][5];
    __shared__ float bc[2];
    #pragma unroll
    for (int o = 16; o > 0; o >>= 1) {
        aa  += __shfl_down_sync(0xffffffffu, aa,  o);
        qq  += __shfl_down_sync(0xffffffffu, qq,  o);
        qa  += __shfl_down_sync(0xffffffffu, qa,  o);
        xp  += __shfl_down_sync(0xffffffffu, xp,  o);
        s0p += __shfl_down_sync(0xffffffffu, s0p, o);
    }
    if ((k & 31) == 0) {
        int w = k >> 5;
        sm[w][0] = aa; sm[w][1] = qq; sm[w][2] = qa; sm[w][3] = xp; sm[w][4] = s0p;
    }
    __syncthreads();

    if (k == 0) {
        float taa = 0.f, tqq = 0.f, tqa = 0.f, txp = 0.f, ts0 = 0.f;
        #pragma unroll
        for (int i = 0; i < 6; ++i) {
            taa += sm[i][0]; tqq += sm[i][1]; tqa += sm[i][2];
            txp += sm[i][3]; ts0 += sm[i][4];
        }
        const float hh    = txp + 1.0f;            // ||h1||^2
        const float invNa = rsqrtf(taa);           // 1/||A_raw||
        const float qA    = tqa * invNa;           // q . Ahat
        const float cc    = 2.0f * LR;
        const float eps   = LR * LAM;

        float p = 0.f, aH = 0.f, beta = 1.0f;
        for (int t = 0; t < ITRS; ++t) {
            float qu = p * tqq + aH * qA;                          // q.u
            float uu = p * p * tqq + 2.0f * p * aH * qA + aH * aH; // ||u||^2
            float v  = beta * beta * ts0 + 2.0f * beta * qu + hh * uu;
            float alpha = 1.0f - eps * rsqrtf(v);                  // 1 - eps/||W||
            float m = alpha - cc * hh;
            float pn = m * p - cc * beta;
            aH = m * aH + cc;
            p = pn;
            beta *= alpha;
        }
        bc[0] = p;
        bc[1] = aH * invNa;    // coefficient on A_raw
        g_beta[n] = beta;
    }
    __syncthreads();

    ((float*)g_u4)[n * N1 + k] = bc[0] * q + bc[1] * A;
}

// ---------------------------------------------------------------------------
// Pass C: W_all = beta_n * W0 + h1 * u^T.  1536 blocks (2 waves), __stcs
// streaming stores. PDL: launch overlaps pass B; sync before reading u/beta.
// ---------------------------------------------------------------------------
__global__ void __launch_bounds__(256) outC_kernel(
    const float* __restrict__ x,
    const float* __restrict__ W0,
    float* __restrict__ out)   // points at d_out + 512
{
    const int n = blockIdx.x % N2;
    const int c = blockIdx.x / N2;
    const int t = threadIdx.x;

    cudaGridDependencySynchronize();   // wait for pass B's u / beta

    if (t < 240) {
        const int k4 = t % K4;
        const int dr = t / K4;                 // 0..4
        const int d0 = c * DPCC;
        const int dEnd = (d0 + DPCC < D1) ? (d0 + DPCC) : D1;

        const float4 uv = g_u4[n * K4 + k4];   // hoisted: constant per thread
        const float  b  = g_beta[n];

        const size_t base = (size_t)n * D1 * K4 + k4;
        const float4* w04 = (const float4*)W0 + base;
        float4*       o4  = (float4*)out + base;

        #pragma unroll 4
        for (int d = d0 + dr; d < dEnd; d += 5) {
            const float h = (d < D_IN) ? __ldg(x + d) : 1.0f;
            float4 w = __ldg(w04 + (size_t)d * K4);
            float4 o;
            o.x = fmaf(b, w.x, h * uv.x);
            o.y = fmaf(b, w.y, h * uv.y);
            o.z = fmaf(b, w.z, h * uv.z);
            o.w = fmaf(b, w.w, h * uv.w);
            __stcs(o4 + (size_t)d * K4, o);    // streaming store: evict-first
        }
    }
}

// ---------------------------------------------------------------------------
extern "C" void kernel_launch(void* const* d_in, const int* in_sizes, int n_in,
                              void* d_out, int out_size)
{
    const float* x  = (const float*)d_in[0];
    const float* We = (const float*)d_in[1];
    const float* W0 = (const float*)d_in[2];
    const float* Wp = (const float*)d_in[3];
    const float* bp = (const float*)d_in[4];
    float* out = (float*)d_out;

    // Pass A: stream We + W0 -> partials; pred fused in as extra blocks
    fusedA_kernel<<<NB_RED + NB_PRED, 256>>>(x, We, W0, Wp, bp, out);

    // Pass B with PDL: overlaps launch + x-prologue with A's drain
    {
        cudaLaunchConfig_t cfg = {};
        cfg.gridDim  = dim3(N2);
        cfg.blockDim = dim3(N1);
        cudaLaunchAttribute attr[1];
        attr[0].id = cudaLaunchAttributeProgrammaticStreamSerialization;
        attr[0].val.programmaticStreamSerializationAllowed = 1;
        cfg.attrs = attr;
        cfg.numAttrs = 1;
        cudaLaunchKernelEx(&cfg, iterB_kernel, x);
    }

    // Pass C with PDL: launch overlaps B; syncs before reading u/beta
    {
        cudaLaunchConfig_t cfg = {};
        cfg.gridDim  = dim3(NB_C);
        cfg.blockDim = dim3(256);
        cudaLaunchAttribute attr[1];
        attr[0].id = cudaLaunchAttributeProgrammaticStreamSerialization;
        attr[0].val.programmaticStreamSerializationAllowed = 1;
        cfg.attrs = attr;
        cfg.numAttrs = 1;
        cudaLaunchKernelEx(&cfg, outC_kernel, x, W0, (float*)d_out + D_OUT);
    }
}